// round 6
// baseline (speedup 1.0000x reference)
#include <cuda_runtime.h>

#define BATCH 16
#define TLEN  512
#define DIMSZ 384
#define DMAX  4096
#define MAIN  (BATCH * DIMSZ * DMAX)   // 25,165,824 floats
#define ROWS  8                        // d-rows per block

// ---------------------------------------------------------------------------
// Fused single-wave kernel: grid (48, 16) = 768 blocks x 256 threads,
// 6 blocks/SM -> every block resident (one wave, no transitions).
// Each block:
//  1. stages its ROWS x-rows (16 KB) into smem,
//  2. re-runs the 512-duration inclusive scan (warp shuffles),
//  3. scatters timestep ids into an int16 smem idx array (pad = -1),
//  4. per idx quad (LDS.64): 32 independent smem gathers feeding
//     8 independent streaming STG.128 -> deep MLP per scoreboard wait.
// ---------------------------------------------------------------------------
__global__ void __launch_bounds__(256, 6) length_regulator_kernel(
    const float* __restrict__ x, const int* __restrict__ dur,
    float* __restrict__ out, int out_size)
{
    const int b   = blockIdx.y;
    const int dg  = blockIdx.x;          // 0..47
    const int tid = threadIdx.x;         // 0..255
    const int d0  = dg * ROWS;

    __shared__ short s_idx[DMAX];        //  8 KB (indices < 512 fit in int16)
    __shared__ float s_x[ROWS * TLEN];   // 16 KB
    __shared__ int   wsum[8], woff[8];

    // ---- stage x rows (1024 float4, 4/thread, coalesced) ----
    const float4* xb4 = reinterpret_cast<const float4*>(
        x + ((size_t)b * DIMSZ + d0) * TLEN);
    #pragma unroll
    for (int k = 0; k < 4; k++)
        reinterpret_cast<float4*>(s_x)[k * 256 + tid] = xb4[k * 256 + tid];

    // ---- init idx to -1 (0xFFFF shorts via int writes: 2048 ints, 8/thread)
    #pragma unroll
    for (int k = 0; k < 8; k++)
        reinterpret_cast<int*>(s_idx)[k * 256 + tid] = -1;

    // ---- scan 512 durations with 256 threads (2 adjacent steps/thread) ----
    const int2 dd = reinterpret_cast<const int2*>(dur + b * TLEN)[tid];
    int da = dd.x, db = dd.y;
    const int lane = tid & 31;
    const int wid  = tid >> 5;           // 0..7

    int v = da + db;                     // pair sum
    const int pair = v;
    #pragma unroll
    for (int o = 1; o < 32; o <<= 1) {
        int n = __shfl_up_sync(0xffffffffu, v, o);
        if (lane >= o) v += n;
    }
    if (lane == 31) wsum[wid] = v;
    __syncthreads();
    if (tid < 8) {
        int w = wsum[tid];
        #pragma unroll
        for (int o = 1; o < 8; o <<= 1) {
            int n = __shfl_up_sync(0x000000ffu, w, o);
            if (tid >= o) w += n;
        }
        woff[tid] = w;
    }
    __syncthreads();

    const int total = woff[7];
    int c0, c1, mel;
    if (total == 0) {                    // all-zero row: duration := 1
        da = 1; db = 1;
        c0 = 2 * tid + 1;
        c1 = 2 * tid + 2;
        mel = TLEN;
    } else {
        const int excl = v - pair + (wid ? woff[wid - 1] : 0);
        c0 = excl + da;
        c1 = c0 + db;
        mel = total;
    }

    // ---- scatter timestep ids into smem idx (disjoint ranges) ----
    {
        const short t0 = (short)(2 * tid), t1 = (short)(2 * tid + 1);
        int s0 = c0 - da;
        for (int k = 0; k < da; k++) s_idx[s0 + k] = t0;
        int s1 = c1 - db;
        for (int k = 0; k < db; k++) s_idx[s1 + k] = t1;
    }
    __syncthreads();

    // ---- gather + streaming stores ----
    float* ob = out + ((size_t)b * DIMSZ + d0) * DMAX;

    #pragma unroll
    for (int s = 0; s < 4; s++) {
        const int slot = s * 256 + tid;              // float4 slot 0..1023
        const short4 iv = reinterpret_cast<const short4*>(s_idx)[slot];
        const int i0 = iv.x, i1 = iv.y, i2 = iv.z, i3 = iv.w;
        #pragma unroll
        for (int r = 0; r < ROWS; r++) {
            const float* sx = s_x + r * TLEN;
            float4 val;
            val.x = (i0 >= 0) ? sx[i0] : 0.0f;
            val.y = (i1 >= 0) ? sx[i1] : 0.0f;
            val.z = (i2 >= 0) ? sx[i2] : 0.0f;
            val.w = (i3 >= 0) ? sx[i3] : 0.0f;
            __stcs(reinterpret_cast<float4*>(ob + (size_t)r * DMAX) + slot, val);
        }
    }

    // ---- mel_len output + tail zeroing ----
    if (dg == 0) {
        if (tid == 0 && out_size >= MAIN + BATCH)
            out[MAIN + b] = (float)mel;
        if (b == 0) {
            for (int p = MAIN + BATCH + tid; p < out_size; p += 256)
                out[p] = 0.0f;
        }
    }
}

extern "C" void kernel_launch(void* const* d_in, const int* in_sizes, int n_in,
                              void* d_out, int out_size)
{
    const float* x   = (const float*)d_in[0];   // (16, 384, 512) f32
    const int*   dur = (const int*)d_in[1];     // (16, 512) i32
    float*       out = (float*)d_out;

    length_regulator_kernel<<<dim3(DIMSZ / ROWS, BATCH), 256>>>(x, dur, out, out_size);
}

// round 7
// speedup vs baseline: 1.0122x; 1.0122x over previous
#include <cuda_runtime.h>

#define BATCH 16
#define TLEN  512
#define DIMSZ 384
#define DMAX  4096
#define MAIN  (BATCH * DIMSZ * DMAX)   // 25,165,824 floats
#define ROWS  4                        // d-rows per block

// ---------------------------------------------------------------------------
// Fused kernel: grid (96, 16) = 1536 blocks x 256 threads (R5's best shape).
// Each block:
//  1. stages its ROWS x-rows (8 KB) into smem,
//  2. re-runs the 512-duration inclusive scan (warp shuffles),
//  3. scatters timestep ids into an int16 smem idx array (pad = -1),
//  4. gathers from smem and streams float4 stores.
// NEW: warp-uniform pad fast path — frames are monotonic, so a warp whose
// first frame is >= mel_len stores zeros directly (no idx load, no gather
// LDS). On average ~56% of frames are padding, cutting smem traffic >2x.
// ---------------------------------------------------------------------------
__global__ void __launch_bounds__(256, 8) length_regulator_kernel(
    const float* __restrict__ x, const int* __restrict__ dur,
    float* __restrict__ out, int out_size)
{
    const int b   = blockIdx.y;
    const int dg  = blockIdx.x;          // 0..95
    const int tid = threadIdx.x;         // 0..255
    const int d0  = dg * ROWS;

    __shared__ short s_idx[DMAX];        // 8 KB (indices < 512 fit in int16)
    __shared__ float s_x[ROWS * TLEN];   // 8 KB
    __shared__ int   wsum[8], woff[8];

    // ---- stage x rows (512 float4, 2/thread, coalesced) ----
    const float4* xb4 = reinterpret_cast<const float4*>(
        x + ((size_t)b * DIMSZ + d0) * TLEN);
    reinterpret_cast<float4*>(s_x)[tid]       = xb4[tid];
    reinterpret_cast<float4*>(s_x)[tid + 256] = xb4[tid + 256];

    // ---- init idx to -1 (0xFFFF shorts via int writes: 2048 ints, 8/thread)
    #pragma unroll
    for (int k = 0; k < 8; k++)
        reinterpret_cast<int*>(s_idx)[k * 256 + tid] = -1;

    // ---- scan 512 durations with 256 threads (2 adjacent steps/thread) ----
    const int2 dd = reinterpret_cast<const int2*>(dur + b * TLEN)[tid];
    int da = dd.x, db = dd.y;
    const int lane = tid & 31;
    const int wid  = tid >> 5;           // 0..7

    int v = da + db;                     // pair sum
    const int pair = v;
    #pragma unroll
    for (int o = 1; o < 32; o <<= 1) {
        int n = __shfl_up_sync(0xffffffffu, v, o);
        if (lane >= o) v += n;
    }
    if (lane == 31) wsum[wid] = v;
    __syncthreads();
    if (tid < 8) {
        int w = wsum[tid];
        #pragma unroll
        for (int o = 1; o < 8; o <<= 1) {
            int n = __shfl_up_sync(0x000000ffu, w, o);
            if (tid >= o) w += n;
        }
        woff[tid] = w;
    }
    __syncthreads();

    const int total = woff[7];
    int c0, c1, mel;
    if (total == 0) {                    // all-zero row: duration := 1
        da = 1; db = 1;
        c0 = 2 * tid + 1;
        c1 = 2 * tid + 2;
        mel = TLEN;
    } else {
        const int excl = v - pair + (wid ? woff[wid - 1] : 0);
        c0 = excl + da;
        c1 = c0 + db;
        mel = total;
    }

    // ---- scatter timestep ids into smem idx (disjoint ranges) ----
    {
        const short t0 = (short)(2 * tid), t1 = (short)(2 * tid + 1);
        int s0 = c0 - da;
        for (int k = 0; k < da; k++) s_idx[s0 + k] = t0;
        int s1 = c1 - db;
        for (int k = 0; k < db; k++) s_idx[s1 + k] = t1;
    }
    __syncthreads();

    // ---- gather + streaming stores, warp-uniform pad fast path ----
    float* ob = out + ((size_t)b * DIMSZ + d0) * DMAX;
    const int warp_base = tid & ~31;     // lane-uniform

    #pragma unroll
    for (int s = 0; s < 4; s++) {
        const int slot = s * 256 + tid;              // float4 slot 0..1023

        if ((s * 256 + warp_base) * 4 >= mel) {
            // whole warp range is padding: pure zero stores
            const float4 z = make_float4(0.f, 0.f, 0.f, 0.f);
            #pragma unroll
            for (int r = 0; r < ROWS; r++)
                __stcs(reinterpret_cast<float4*>(ob + (size_t)r * DMAX) + slot, z);
        } else {
            const short4 iv = reinterpret_cast<const short4*>(s_idx)[slot];
            const int i0 = iv.x, i1 = iv.y, i2 = iv.z, i3 = iv.w;
            #pragma unroll
            for (int r = 0; r < ROWS; r++) {
                const float* sx = s_x + r * TLEN;
                float4 val;
                val.x = (i0 >= 0) ? sx[i0] : 0.0f;
                val.y = (i1 >= 0) ? sx[i1] : 0.0f;
                val.z = (i2 >= 0) ? sx[i2] : 0.0f;
                val.w = (i3 >= 0) ? sx[i3] : 0.0f;
                __stcs(reinterpret_cast<float4*>(ob + (size_t)r * DMAX) + slot, val);
            }
        }
    }

    // ---- mel_len output + tail zeroing ----
    if (dg == 0) {
        if (tid == 0 && out_size >= MAIN + BATCH)
            out[MAIN + b] = (float)mel;
        if (b == 0) {
            for (int p = MAIN + BATCH + tid; p < out_size; p += 256)
                out[p] = 0.0f;
        }
    }
}

extern "C" void kernel_launch(void* const* d_in, const int* in_sizes, int n_in,
                              void* d_out, int out_size)
{
    const float* x   = (const float*)d_in[0];   // (16, 384, 512) f32
    const int*   dur = (const int*)d_in[1];     // (16, 512) i32
    float*       out = (float*)d_out;

    length_regulator_kernel<<<dim3(DIMSZ / ROWS, BATCH), 256>>>(x, dur, out, out_size);
}